// round 1
// baseline (speedup 1.0000x reference)
#include <cuda_runtime.h>
#include <cstdint>

// Problem constants (fixed shapes per reference)
#define NN 100000
#define EE 1600000
#define HID 64

// ---------------- device scratch (no allocations allowed) ----------------
__device__ int   g_cnt[NN];
__device__ float g_dinv[NN];
__device__ int   g_rowptr[NN + 1];
__device__ int   g_fill[NN];
__device__ int   g_col[EE];
__device__ __align__(16) float g_h1[(size_t)NN * HID];  // gemm output buffer
__device__ __align__(16) float g_ha[(size_t)NN * HID];  // post-aggregation activations
__device__ int   g_is64;

// ---------------- edge dtype detection (int64 vs int32) ----------------
__global__ void detect_kernel(const void* ei) {
    if (threadIdx.x == 0 && blockIdx.x == 0) {
        const long long* p = (const long long*)ei;
        int ok64 = 1;
        for (int i = 0; i < 256; i++) {
            long long v = p[i];
            if (v < 0 || v >= NN) { ok64 = 0; break; }
        }
        g_is64 = ok64;
    }
}

__device__ __forceinline__ int edge_val(const void* ei, int idx) {
    if (g_is64) return (int)((const long long*)ei)[idx];
    return ((const int*)ei)[idx];
}

// ---------------- degree / CSR build ----------------
__global__ void zero_cnt_kernel(int n) {
    int i = blockIdx.x * blockDim.x + threadIdx.x;
    if (i < n) g_cnt[i] = 0;
}

__global__ void count_kernel(const void* ei, int E) {
    int e = blockIdx.x * blockDim.x + threadIdx.x;
    if (e < E) {
        int dst = edge_val(ei, E + e);
        atomicAdd(&g_cnt[dst], 1);
    }
}

__global__ void dinv_kernel(int n) {
    int i = blockIdx.x * blockDim.x + threadIdx.x;
    if (i < n) {
        g_dinv[i] = rsqrtf((float)(g_cnt[i] + 1));  // +1 self-loop
        g_fill[i] = 0;
    }
}

// single-block exclusive scan over g_cnt -> g_rowptr (n % 4 == 0 assumed)
__global__ void scan_kernel(int n) {
    const int tid = threadIdx.x;
    __shared__ int wsum[32];
    __shared__ int carry;
    if (tid == 0) carry = 0;
    __syncthreads();
    const int4* c4 = (const int4*)g_cnt;
    int nv4 = n >> 2;
    for (int base = 0; base < nv4; base += 1024) {
        int idx = base + tid;
        int4 v = make_int4(0, 0, 0, 0);
        if (idx < nv4) v = c4[idx];
        int s = v.x + v.y + v.z + v.w;
        int x = s;
        #pragma unroll
        for (int o = 1; o < 32; o <<= 1) {
            int y = __shfl_up_sync(0xffffffffu, x, o);
            if ((tid & 31) >= o) x += y;
        }
        if ((tid & 31) == 31) wsum[tid >> 5] = x;
        __syncthreads();
        if (tid < 32) {
            int w = wsum[tid];
            #pragma unroll
            for (int o = 1; o < 32; o <<= 1) {
                int y = __shfl_up_sync(0xffffffffu, w, o);
                if (tid >= o) w += y;
            }
            wsum[tid] = w;
        }
        __syncthreads();
        int excl = x - s + ((tid >= 32) ? wsum[(tid >> 5) - 1] : 0) + carry;
        if (idx < nv4) {
            g_rowptr[idx * 4 + 0] = excl;
            g_rowptr[idx * 4 + 1] = excl + v.x;
            g_rowptr[idx * 4 + 2] = excl + v.x + v.y;
            g_rowptr[idx * 4 + 3] = excl + v.x + v.y + v.z;
        }
        __syncthreads();
        if (tid == 1023) carry = excl + s;
        __syncthreads();
    }
    if (tid == 0) g_rowptr[n] = carry;
}

__global__ void scatter_kernel(const void* ei, int E) {
    int e = blockIdx.x * blockDim.x + threadIdx.x;
    if (e < E) {
        int src = edge_val(ei, e);
        int dst = edge_val(ei, E + e);
        int pos = g_rowptr[dst] + atomicAdd(&g_fill[dst], 1);
        g_col[pos] = src;
    }
}

// ---------------- GEMM: [M,K] @ [K,64] -> [M,64], fp32 ----------------
// 64x64 block tile, BK=64, 256 threads, 4x4 accumulators per thread.
template <int K>
__global__ void gemm_kernel(const float* __restrict__ A,
                            const float* __restrict__ B,
                            float* __restrict__ C, int M) {
    __shared__ float xs[64][68];   // [row][k], padded (store float4, read scalar)
    __shared__ float ws[64][64];   // [k][col]
    const int tid = threadIdx.x;
    const int tx = tid & 15, ty = tid >> 4;
    const int row0 = blockIdx.x * 64;

    float acc[4][4] = {};

    for (int kt = 0; kt < K; kt += 64) {
        #pragma unroll
        for (int it = 0; it < 4; it++) {
            int f = tid + it * 256;
            int r = f >> 4, c4 = f & 15;
            int grow = row0 + r;
            float4 v = make_float4(0.f, 0.f, 0.f, 0.f);
            if (grow < M) v = *(const float4*)&A[(size_t)grow * K + kt + c4 * 4];
            *(float4*)&xs[r][c4 * 4] = v;
        }
        #pragma unroll
        for (int it = 0; it < 4; it++) {
            int f = tid + it * 256;
            int kk = f >> 4, c4 = f & 15;
            *(float4*)&ws[kk][c4 * 4] = *(const float4*)&B[(size_t)(kt + kk) * 64 + c4 * 4];
        }
        __syncthreads();
        #pragma unroll
        for (int k = 0; k < 64; k++) {
            float4 b = *(float4*)&ws[k][tx * 4];
            #pragma unroll
            for (int r = 0; r < 4; r++) {
                float a = xs[ty * 4 + r][k];
                acc[r][0] += a * b.x;
                acc[r][1] += a * b.y;
                acc[r][2] += a * b.z;
                acc[r][3] += a * b.w;
            }
        }
        __syncthreads();
    }
    #pragma unroll
    for (int r = 0; r < 4; r++) {
        int grow = row0 + ty * 4 + r;
        if (grow < M)
            *(float4*)&C[(size_t)grow * 64 + tx * 4] =
                make_float4(acc[r][0], acc[r][1], acc[r][2], acc[r][3]);
    }
}

// ---------------- aggregation: one warp per node, CSR gather ----------------
__global__ void agg_kernel(const float* __restrict__ h,
                           const float* __restrict__ bias,
                           float* __restrict__ out, int n) {
    int wid = (blockIdx.x * blockDim.x + threadIdx.x) >> 5;
    int lane = threadIdx.x & 31;
    if (wid >= n) return;
    int i = wid;
    float di = g_dinv[i];
    float self = di * di;
    float a0 = self * h[i * 64 + lane];
    float a1 = self * h[i * 64 + 32 + lane];
    int e = g_rowptr[i];
    int end = g_rowptr[i + 1];
    for (; e + 1 < end; e += 2) {
        int s0 = g_col[e];
        int s1 = g_col[e + 1];
        float w0 = g_dinv[s0] * di;
        float w1 = g_dinv[s1] * di;
        a0 += w0 * h[s0 * 64 + lane];
        a1 += w0 * h[s0 * 64 + 32 + lane];
        a0 += w1 * h[s1 * 64 + lane];
        a1 += w1 * h[s1 * 64 + 32 + lane];
    }
    if (e < end) {
        int s0 = g_col[e];
        float w0 = g_dinv[s0] * di;
        a0 += w0 * h[s0 * 64 + lane];
        a1 += w0 * h[s0 * 64 + 32 + lane];
    }
    a0 += bias[lane];
    a1 += bias[lane + 32];
    out[i * 64 + lane] = fmaxf(a0, 0.f);
    out[i * 64 + 32 + lane] = fmaxf(a1, 0.f);
}

// ---------------- final FC: [M,64] @ [64,11] + b ----------------
__global__ void fc_kernel(const float* __restrict__ h,
                          const float* __restrict__ W,
                          const float* __restrict__ b,
                          float* __restrict__ out, int M) {
    __shared__ float ws[64 * 11];
    __shared__ float bs[11];
    int tid = threadIdx.x;
    for (int i = tid; i < 64 * 11; i += 256) ws[i] = W[i];
    if (tid < 11) bs[tid] = b[tid];
    __syncthreads();
    int row = blockIdx.x * 256 + tid;
    if (row >= M) return;
    float acc[11];
    #pragma unroll
    for (int j = 0; j < 11; j++) acc[j] = bs[j];
    const float4* h4 = (const float4*)(h + (size_t)row * 64);
    #pragma unroll
    for (int q = 0; q < 16; q++) {
        float4 v = h4[q];
        #pragma unroll
        for (int j = 0; j < 11; j++) {
            acc[j] += v.x * ws[(q * 4 + 0) * 11 + j];
            acc[j] += v.y * ws[(q * 4 + 1) * 11 + j];
            acc[j] += v.z * ws[(q * 4 + 2) * 11 + j];
            acc[j] += v.w * ws[(q * 4 + 3) * 11 + j];
        }
    }
    #pragma unroll
    for (int j = 0; j < 11; j++) out[(size_t)row * 11 + j] = acc[j];
}

// ---------------- launch ----------------
extern "C" void kernel_launch(void* const* d_in, const int* in_sizes, int n_in,
                              void* d_out, int out_size) {
    const float* x   = (const float*)d_in[0];
    const void*  ei  = d_in[1];
    const float* W1  = (const float*)d_in[2];
    const float* b1  = (const float*)d_in[3];
    const float* W2  = (const float*)d_in[4];
    const float* b2  = (const float*)d_in[5];
    const float* Wfc = (const float*)d_in[6];
    const float* bfc = (const float*)d_in[7];
    float* out = (float*)d_out;

    const int n = in_sizes[0] / 256;   // 100000
    const int E = in_sizes[1] / 2;     // 1600000 (element count is 2E for both dtypes)

    const int TB = 256;
    int nb_node = (n + TB - 1) / TB;
    int nb_edge = (E + TB - 1) / TB;
    int nb_gemm = (n + 63) / 64;
    int nb_agg  = (n * 32 + TB - 1) / TB;

    detect_kernel<<<1, 32>>>(ei);
    zero_cnt_kernel<<<nb_node, TB>>>(n);
    count_kernel<<<nb_edge, TB>>>(ei, E);
    dinv_kernel<<<nb_node, TB>>>(n);
    scan_kernel<<<1, 1024>>>(n);
    scatter_kernel<<<nb_edge, TB>>>(ei, E);

    // layer 1
    gemm_kernel<256><<<nb_gemm, TB>>>(x, W1, g_h1, n);
    agg_kernel<<<nb_agg, TB>>>(g_h1, b1, g_ha, n);

    // layer 2
    gemm_kernel<64><<<nb_gemm, TB>>>(g_ha, W2, g_h1, n);
    agg_kernel<<<nb_agg, TB>>>(g_h1, b2, g_ha, n);

    // classifier
    fc_kernel<<<nb_node, TB>>>(g_ha, Wfc, bfc, out, n);
}

// round 2
// speedup vs baseline: 1.1454x; 1.1454x over previous
#include <cuda_runtime.h>
#include <cstdint>

// Problem constants (fixed shapes per reference)
#define NN 100000
#define EE 1600000
#define HID 64

// ---------------- device scratch (no allocations allowed) ----------------
__device__ int   g_cnt[NN];
__device__ float g_dinv[NN];
__device__ int   g_rowptr[NN + 1];
__device__ int   g_fill[NN];
__device__ int   g_col[EE];
__device__ __align__(16) float g_h1[(size_t)NN * HID];  // gemm output (dinv-premultiplied)
__device__ __align__(16) float g_ha[(size_t)NN * HID];  // post-aggregation activations
__device__ int   g_is64;

// ---------------- init: zero counters + edge dtype detection ----------------
__global__ void init_kernel(const void* ei, int n) {
    int i = blockIdx.x * blockDim.x + threadIdx.x;
    if (i * 4 < n) *(int4*)&g_cnt[i * 4] = make_int4(0, 0, 0, 0);
    if (i == 0) {
        const long long* p = (const long long*)ei;
        int ok64 = 1;
        #pragma unroll 1
        for (int k = 0; k < 64; k++) {
            long long v = p[k];
            if (v < 0 || v >= NN) { ok64 = 0; break; }
        }
        g_is64 = ok64;
    }
}

// ---------------- degree count ----------------
__global__ __launch_bounds__(256) void count_kernel(const void* ei, int E) {
    int e = blockIdx.x * blockDim.x + threadIdx.x;
    if (e >= E) return;
    int dst = g_is64 ? (int)((const long long*)ei)[E + e] : ((const int*)ei)[E + e];
    atomicAdd(&g_cnt[dst], 1);
}

// single-block exclusive scan over g_cnt -> g_rowptr; also dinv + fill init
__global__ __launch_bounds__(1024) void scan_kernel(int n) {
    const int tid = threadIdx.x;
    __shared__ int wsum[32];
    __shared__ int carry;
    if (tid == 0) carry = 0;
    __syncthreads();
    const int4* c4 = (const int4*)g_cnt;
    int nv4 = n >> 2;
    for (int base = 0; base < nv4; base += 1024) {
        int idx = base + tid;
        int4 v = make_int4(0, 0, 0, 0);
        if (idx < nv4) v = c4[idx];
        int s = v.x + v.y + v.z + v.w;
        int x = s;
        #pragma unroll
        for (int o = 1; o < 32; o <<= 1) {
            int y = __shfl_up_sync(0xffffffffu, x, o);
            if ((tid & 31) >= o) x += y;
        }
        if ((tid & 31) == 31) wsum[tid >> 5] = x;
        __syncthreads();
        if (tid < 32) {
            int w = wsum[tid];
            #pragma unroll
            for (int o = 1; o < 32; o <<= 1) {
                int y = __shfl_up_sync(0xffffffffu, w, o);
                if (tid >= o) w += y;
            }
            wsum[tid] = w;
        }
        __syncthreads();
        int excl = x - s + ((tid >= 32) ? wsum[(tid >> 5) - 1] : 0) + carry;
        if (idx < nv4) {
            g_rowptr[idx * 4 + 0] = excl;
            g_rowptr[idx * 4 + 1] = excl + v.x;
            g_rowptr[idx * 4 + 2] = excl + v.x + v.y;
            g_rowptr[idx * 4 + 3] = excl + v.x + v.y + v.z;
            *(float4*)&g_dinv[idx * 4] = make_float4(
                rsqrtf((float)(v.x + 1)), rsqrtf((float)(v.y + 1)),
                rsqrtf((float)(v.z + 1)), rsqrtf((float)(v.w + 1)));
            *(int4*)&g_fill[idx * 4] = make_int4(0, 0, 0, 0);
        }
        __syncthreads();
        if (tid == 1023) carry = excl + s;
        __syncthreads();
    }
    if (tid == 0) g_rowptr[n] = carry;
}

__global__ __launch_bounds__(256) void scatter_kernel(const void* ei, int E) {
    int e = blockIdx.x * blockDim.x + threadIdx.x;
    if (e >= E) return;
    int src, dst;
    if (g_is64) {
        src = (int)((const long long*)ei)[e];
        dst = (int)((const long long*)ei)[E + e];
    } else {
        src = ((const int*)ei)[e];
        dst = ((const int*)ei)[E + e];
    }
    int pos = g_rowptr[dst] + atomicAdd(&g_fill[dst], 1);
    g_col[pos] = src;
}

// ---------------- GEMM: [M,K] @ [K,64] -> dinv[row] * result ----------------
// 128x64 block tile, BK=32, 256 threads, 8x4 accumulators per thread.
template <int K>
__global__ __launch_bounds__(256) void gemm_dinv_kernel(const float* __restrict__ A,
                                                        const float* __restrict__ B,
                                                        float* __restrict__ C, int M) {
    __shared__ float xs[128][32];  // [row][k]
    __shared__ float ws[32][64];   // [k][col]
    const int tid = threadIdx.x;
    const int tx = tid & 15, ty = tid >> 4;
    const int row0 = blockIdx.x * 128;

    float acc[8][4] = {};

    for (int kt = 0; kt < K; kt += 32) {
        #pragma unroll
        for (int it = 0; it < 4; it++) {
            int idx = tid + it * 256;
            int r = idx >> 3, c4 = idx & 7;
            int grow = row0 + r;
            float4 v = make_float4(0.f, 0.f, 0.f, 0.f);
            if (grow < M) v = *(const float4*)&A[(size_t)grow * K + kt + c4 * 4];
            *(float4*)&xs[r][c4 * 4] = v;
        }
        #pragma unroll
        for (int it = 0; it < 2; it++) {
            int idx = tid + it * 256;
            int kk = idx >> 4, c4 = idx & 15;
            *(float4*)&ws[kk][c4 * 4] = *(const float4*)&B[(size_t)(kt + kk) * 64 + c4 * 4];
        }
        __syncthreads();
        #pragma unroll
        for (int k = 0; k < 32; k++) {
            float4 b = *(float4*)&ws[k][tx * 4];
            #pragma unroll
            for (int r = 0; r < 8; r++) {
                float a = xs[ty * 8 + r][k];
                acc[r][0] += a * b.x;
                acc[r][1] += a * b.y;
                acc[r][2] += a * b.z;
                acc[r][3] += a * b.w;
            }
        }
        __syncthreads();
    }
    #pragma unroll
    for (int r = 0; r < 8; r++) {
        int grow = row0 + ty * 8 + r;
        if (grow < M) {
            float di = g_dinv[grow];
            *(float4*)&C[(size_t)grow * 64 + tx * 4] =
                make_float4(di * acc[r][0], di * acc[r][1], di * acc[r][2], di * acc[r][3]);
        }
    }
}

// ---------------- aggregation: one warp per node, gather-sum of hs rows ----------------
// hs[i] = dinv[i] * (x@W)[i];  out[d] = relu(dinv[d]*(sum hs[col] + hs[d]) + bias)
__global__ __launch_bounds__(256) void agg_relu_kernel(const float2* __restrict__ hs,
                                                       const float* __restrict__ bias,
                                                       float2* __restrict__ out, int n) {
    int wid = (blockIdx.x * blockDim.x + threadIdx.x) >> 5;
    int lane = threadIdx.x & 31;
    if (wid >= n) return;
    const int i = wid;
    float2 self = hs[(size_t)i * 32 + lane];
    float ax = self.x, ay = self.y;
    int e = g_rowptr[i];
    const int end = g_rowptr[i + 1];
    for (; e + 3 < end; e += 4) {
        int s0 = __ldg(&g_col[e]);
        int s1 = __ldg(&g_col[e + 1]);
        int s2 = __ldg(&g_col[e + 2]);
        int s3 = __ldg(&g_col[e + 3]);
        float2 v0 = hs[(size_t)s0 * 32 + lane];
        float2 v1 = hs[(size_t)s1 * 32 + lane];
        float2 v2 = hs[(size_t)s2 * 32 + lane];
        float2 v3 = hs[(size_t)s3 * 32 + lane];
        ax += v0.x + v1.x + v2.x + v3.x;
        ay += v0.y + v1.y + v2.y + v3.y;
    }
    for (; e < end; e++) {
        int s0 = __ldg(&g_col[e]);
        float2 v0 = hs[(size_t)s0 * 32 + lane];
        ax += v0.x;
        ay += v0.y;
    }
    float di = g_dinv[i];
    float2 bb = ((const float2*)bias)[lane];
    out[(size_t)i * 32 + lane] =
        make_float2(fmaxf(di * ax + bb.x, 0.f), fmaxf(di * ay + bb.y, 0.f));
}

// ---------------- layer-2 aggregation fused with final FC ----------------
__global__ __launch_bounds__(256) void agg_fc_kernel(const float2* __restrict__ hs,
                                                     const float* __restrict__ b2,
                                                     const float* __restrict__ Wfc,
                                                     const float* __restrict__ bfc,
                                                     float* __restrict__ out, int n) {
    __shared__ float Ws[64 * 11];
    __shared__ float bs[11];
    int tid = threadIdx.x;
    for (int q = tid; q < 64 * 11; q += 256) Ws[q] = Wfc[q];
    if (tid < 11) bs[tid] = bfc[tid];
    __syncthreads();

    int wid = (blockIdx.x * blockDim.x + tid) >> 5;
    int lane = tid & 31;
    if (wid >= n) return;
    const int i = wid;
    float2 self = hs[(size_t)i * 32 + lane];
    float ax = self.x, ay = self.y;
    int e = g_rowptr[i];
    const int end = g_rowptr[i + 1];
    for (; e + 3 < end; e += 4) {
        int s0 = __ldg(&g_col[e]);
        int s1 = __ldg(&g_col[e + 1]);
        int s2 = __ldg(&g_col[e + 2]);
        int s3 = __ldg(&g_col[e + 3]);
        float2 v0 = hs[(size_t)s0 * 32 + lane];
        float2 v1 = hs[(size_t)s1 * 32 + lane];
        float2 v2 = hs[(size_t)s2 * 32 + lane];
        float2 v3 = hs[(size_t)s3 * 32 + lane];
        ax += v0.x + v1.x + v2.x + v3.x;
        ay += v0.y + v1.y + v2.y + v3.y;
    }
    for (; e < end; e++) {
        int s0 = __ldg(&g_col[e]);
        float2 v0 = hs[(size_t)s0 * 32 + lane];
        ax += v0.x;
        ay += v0.y;
    }
    float di = g_dinv[i];
    float2 bb = ((const float2*)b2)[lane];
    float vx = fmaxf(di * ax + bb.x, 0.f);
    float vy = fmaxf(di * ay + bb.y, 0.f);

    // fused FC: lane holds features 2*lane, 2*lane+1
    #pragma unroll
    for (int j = 0; j < 11; j++) {
        float p = vx * Ws[(2 * lane) * 11 + j] + vy * Ws[(2 * lane + 1) * 11 + j];
        #pragma unroll
        for (int o = 16; o; o >>= 1) p += __shfl_xor_sync(0xffffffffu, p, o);
        if (lane == j) out[(size_t)i * 11 + j] = p + bs[j];
    }
}

// ---------------- launch ----------------
extern "C" void kernel_launch(void* const* d_in, const int* in_sizes, int n_in,
                              void* d_out, int out_size) {
    const float* x   = (const float*)d_in[0];
    const void*  ei  = d_in[1];
    const float* W1  = (const float*)d_in[2];
    const float* b1  = (const float*)d_in[3];
    const float* W2  = (const float*)d_in[4];
    const float* b2  = (const float*)d_in[5];
    const float* Wfc = (const float*)d_in[6];
    const float* bfc = (const float*)d_in[7];
    float* out = (float*)d_out;

    const int n = in_sizes[0] / 256;   // 100000
    const int E = in_sizes[1] / 2;     // 1600000

    const int TB = 256;
    int nb_init = (n / 4 + TB - 1) / TB;
    int nb_edge = (E + TB - 1) / TB;
    int nb_gemm = (n + 127) / 128;
    int nb_agg  = (n * 32 + TB - 1) / TB;

    init_kernel<<<nb_init, TB>>>(ei, n);
    count_kernel<<<nb_edge, TB>>>(ei, E);
    scan_kernel<<<1, 1024>>>(n);

    // layer 1 transform (independent of CSR; placed here so ncu -s5 lands on heavy work)
    gemm_dinv_kernel<256><<<nb_gemm, TB>>>(x, W1, g_h1, n);
    scatter_kernel<<<nb_edge, TB>>>(ei, E);
    agg_relu_kernel<<<nb_agg, TB>>>((const float2*)g_h1, b1, (float2*)g_ha, n);

    // layer 2
    gemm_dinv_kernel<64><<<nb_gemm, TB>>>(g_ha, W2, g_h1, n);
    agg_fc_kernel<<<nb_agg, TB>>>((const float2*)g_h1, b2, Wfc, bfc, out, n);
}

// round 3
// speedup vs baseline: 1.1471x; 1.0015x over previous
#include <cuda_runtime.h>
#include <cstdint>

// Problem constants (fixed shapes per reference)
#define NN 100000
#define EE 1600000
#define HID 64

// ---------------- device scratch (no allocations allowed) ----------------
__device__ int   g_cnt[NN];
__device__ float g_dinv[NN];
__device__ int   g_rowptr[NN + 1];
__device__ int   g_fill[NN];
__device__ int   g_col[EE];
__device__ __align__(16) float g_h1[(size_t)NN * HID];  // gemm output (dinv-premultiplied)
__device__ __align__(16) float g_ha[(size_t)NN * HID];  // post-aggregation activations
__device__ int   g_is64;

// ---------------- init: zero counters + edge dtype detection ----------------
__global__ void init_kernel(const void* ei, int n) {
    int i = blockIdx.x * blockDim.x + threadIdx.x;
    if (i * 4 < n) *(int4*)&g_cnt[i * 4] = make_int4(0, 0, 0, 0);
    if (i == 0) {
        const long long* p = (const long long*)ei;
        int ok64 = 1;
        #pragma unroll 1
        for (int k = 0; k < 64; k++) {
            long long v = p[k];
            if (v < 0 || v >= NN) { ok64 = 0; break; }
        }
        g_is64 = ok64;
    }
}

// ---------------- degree count ----------------
__global__ __launch_bounds__(256) void count_kernel(const void* ei, int E) {
    int e = blockIdx.x * blockDim.x + threadIdx.x;
    if (e >= E) return;
    int dst = g_is64 ? (int)((const long long*)ei)[E + e] : ((const int*)ei)[E + e];
    atomicAdd(&g_cnt[dst], 1);
}

// single-block exclusive scan over g_cnt -> g_rowptr; also dinv + fill init
__global__ __launch_bounds__(1024) void scan_kernel(int n) {
    const int tid = threadIdx.x;
    __shared__ int wsum[32];
    __shared__ int carry;
    if (tid == 0) carry = 0;
    __syncthreads();
    const int4* c4 = (const int4*)g_cnt;
    int nv4 = n >> 2;
    for (int base = 0; base < nv4; base += 1024) {
        int idx = base + tid;
        int4 v = make_int4(0, 0, 0, 0);
        if (idx < nv4) v = c4[idx];
        int s = v.x + v.y + v.z + v.w;
        int x = s;
        #pragma unroll
        for (int o = 1; o < 32; o <<= 1) {
            int y = __shfl_up_sync(0xffffffffu, x, o);
            if ((tid & 31) >= o) x += y;
        }
        if ((tid & 31) == 31) wsum[tid >> 5] = x;
        __syncthreads();
        if (tid < 32) {
            int w = wsum[tid];
            #pragma unroll
            for (int o = 1; o < 32; o <<= 1) {
                int y = __shfl_up_sync(0xffffffffu, w, o);
                if (tid >= o) w += y;
            }
            wsum[tid] = w;
        }
        __syncthreads();
        int excl = x - s + ((tid >= 32) ? wsum[(tid >> 5) - 1] : 0) + carry;
        if (idx < nv4) {
            g_rowptr[idx * 4 + 0] = excl;
            g_rowptr[idx * 4 + 1] = excl + v.x;
            g_rowptr[idx * 4 + 2] = excl + v.x + v.y;
            g_rowptr[idx * 4 + 3] = excl + v.x + v.y + v.z;
            *(float4*)&g_dinv[idx * 4] = make_float4(
                rsqrtf((float)(v.x + 1)), rsqrtf((float)(v.y + 1)),
                rsqrtf((float)(v.z + 1)), rsqrtf((float)(v.w + 1)));
            *(int4*)&g_fill[idx * 4] = make_int4(0, 0, 0, 0);
        }
        __syncthreads();
        if (tid == 1023) carry = excl + s;
        __syncthreads();
    }
    if (tid == 0) g_rowptr[n] = carry;
}

__global__ __launch_bounds__(256) void scatter_kernel(const void* ei, int E) {
    int e = blockIdx.x * blockDim.x + threadIdx.x;
    if (e >= E) return;
    int src, dst;
    if (g_is64) {
        src = (int)((const long long*)ei)[e];
        dst = (int)((const long long*)ei)[E + e];
    } else {
        src = ((const int*)ei)[e];
        dst = ((const int*)ei)[E + e];
    }
    int pos = g_rowptr[dst] + atomicAdd(&g_fill[dst], 1);
    g_col[pos] = src;
}

// ---------------- GEMM: [M,K] @ [K,64] -> dinv[row] * result ----------------
// 128x64 block tile, BK=32, 256 threads, 8x4 accumulators per thread.
template <int K>
__global__ __launch_bounds__(256) void gemm_dinv_kernel(const float* __restrict__ A,
                                                        const float* __restrict__ B,
                                                        float* __restrict__ C, int M) {
    __shared__ float xs[128][32];  // [row][k]
    __shared__ float ws[32][64];   // [k][col]
    const int tid = threadIdx.x;
    const int tx = tid & 15, ty = tid >> 4;
    const int row0 = blockIdx.x * 128;

    float acc[8][4] = {};

    for (int kt = 0; kt < K; kt += 32) {
        #pragma unroll
        for (int it = 0; it < 4; it++) {
            int idx = tid + it * 256;
            int r = idx >> 3, c4 = idx & 7;
            int grow = row0 + r;
            float4 v = make_float4(0.f, 0.f, 0.f, 0.f);
            if (grow < M) v = *(const float4*)&A[(size_t)grow * K + kt + c4 * 4];
            *(float4*)&xs[r][c4 * 4] = v;
        }
        #pragma unroll
        for (int it = 0; it < 2; it++) {
            int idx = tid + it * 256;
            int kk = idx >> 4, c4 = idx & 15;
            *(float4*)&ws[kk][c4 * 4] = *(const float4*)&B[(size_t)(kt + kk) * 64 + c4 * 4];
        }
        __syncthreads();
        #pragma unroll
        for (int k = 0; k < 32; k++) {
            float4 b = *(float4*)&ws[k][tx * 4];
            #pragma unroll
            for (int r = 0; r < 8; r++) {
                float a = xs[ty * 8 + r][k];
                acc[r][0] += a * b.x;
                acc[r][1] += a * b.y;
                acc[r][2] += a * b.z;
                acc[r][3] += a * b.w;
            }
        }
        __syncthreads();
    }
    #pragma unroll
    for (int r = 0; r < 8; r++) {
        int grow = row0 + ty * 8 + r;
        if (grow < M) {
            float di = g_dinv[grow];
            *(float4*)&C[(size_t)grow * 64 + tx * 4] =
                make_float4(di * acc[r][0], di * acc[r][1], di * acc[r][2], di * acc[r][3]);
        }
    }
}

// ---------------- aggregation: one warp per node, gather-sum of hs rows ----------------
// hs[i] = dinv[i] * (x@W)[i];  out[d] = relu(dinv[d]*(sum hs[col] + hs[d]) + bias)
__global__ __launch_bounds__(256) void agg_relu_kernel(const float2* __restrict__ hs,
                                                       const float* __restrict__ bias,
                                                       float2* __restrict__ out, int n) {
    int wid = (blockIdx.x * blockDim.x + threadIdx.x) >> 5;
    int lane = threadIdx.x & 31;
    if (wid >= n) return;
    const int i = wid;
    float2 self = hs[(size_t)i * 32 + lane];
    float ax = self.x, ay = self.y;
    int e = g_rowptr[i];
    const int end = g_rowptr[i + 1];
    for (; e + 3 < end; e += 4) {
        int s0 = __ldg(&g_col[e]);
        int s1 = __ldg(&g_col[e + 1]);
        int s2 = __ldg(&g_col[e + 2]);
        int s3 = __ldg(&g_col[e + 3]);
        float2 v0 = hs[(size_t)s0 * 32 + lane];
        float2 v1 = hs[(size_t)s1 * 32 + lane];
        float2 v2 = hs[(size_t)s2 * 32 + lane];
        float2 v3 = hs[(size_t)s3 * 32 + lane];
        ax += v0.x + v1.x + v2.x + v3.x;
        ay += v0.y + v1.y + v2.y + v3.y;
    }
    for (; e < end; e++) {
        int s0 = __ldg(&g_col[e]);
        float2 v0 = hs[(size_t)s0 * 32 + lane];
        ax += v0.x;
        ay += v0.y;
    }
    float di = g_dinv[i];
    float2 bb = ((const float2*)bias)[lane];
    out[(size_t)i * 32 + lane] =
        make_float2(fmaxf(di * ax + bb.x, 0.f), fmaxf(di * ay + bb.y, 0.f));
}

// ---------------- layer-2 aggregation fused with final FC ----------------
__global__ __launch_bounds__(256) void agg_fc_kernel(const float2* __restrict__ hs,
                                                     const float* __restrict__ b2,
                                                     const float* __restrict__ Wfc,
                                                     const float* __restrict__ bfc,
                                                     float* __restrict__ out, int n) {
    __shared__ float Ws[64 * 11];
    __shared__ float bs[11];
    int tid = threadIdx.x;
    for (int q = tid; q < 64 * 11; q += 256) Ws[q] = Wfc[q];
    if (tid < 11) bs[tid] = bfc[tid];
    __syncthreads();

    int wid = (blockIdx.x * blockDim.x + tid) >> 5;
    int lane = tid & 31;
    if (wid >= n) return;
    const int i = wid;
    float2 self = hs[(size_t)i * 32 + lane];
    float ax = self.x, ay = self.y;
    int e = g_rowptr[i];
    const int end = g_rowptr[i + 1];
    for (; e + 3 < end; e += 4) {
        int s0 = __ldg(&g_col[e]);
        int s1 = __ldg(&g_col[e + 1]);
        int s2 = __ldg(&g_col[e + 2]);
        int s3 = __ldg(&g_col[e + 3]);
        float2 v0 = hs[(size_t)s0 * 32 + lane];
        float2 v1 = hs[(size_t)s1 * 32 + lane];
        float2 v2 = hs[(size_t)s2 * 32 + lane];
        float2 v3 = hs[(size_t)s3 * 32 + lane];
        ax += v0.x + v1.x + v2.x + v3.x;
        ay += v0.y + v1.y + v2.y + v3.y;
    }
    for (; e < end; e++) {
        int s0 = __ldg(&g_col[e]);
        float2 v0 = hs[(size_t)s0 * 32 + lane];
        ax += v0.x;
        ay += v0.y;
    }
    float di = g_dinv[i];
    float2 bb = ((const float2*)b2)[lane];
    float vx = fmaxf(di * ax + bb.x, 0.f);
    float vy = fmaxf(di * ay + bb.y, 0.f);

    // fused FC: lane holds features 2*lane, 2*lane+1
    #pragma unroll
    for (int j = 0; j < 11; j++) {
        float p = vx * Ws[(2 * lane) * 11 + j] + vy * Ws[(2 * lane + 1) * 11 + j];
        #pragma unroll
        for (int o = 16; o; o >>= 1) p += __shfl_xor_sync(0xffffffffu, p, o);
        if (lane == j) out[(size_t)i * 11 + j] = p + bs[j];
    }
}

// ---------------- launch ----------------
extern "C" void kernel_launch(void* const* d_in, const int* in_sizes, int n_in,
                              void* d_out, int out_size) {
    const float* x   = (const float*)d_in[0];
    const void*  ei  = d_in[1];
    const float* W1  = (const float*)d_in[2];
    const float* b1  = (const float*)d_in[3];
    const float* W2  = (const float*)d_in[4];
    const float* b2  = (const float*)d_in[5];
    const float* Wfc = (const float*)d_in[6];
    const float* bfc = (const float*)d_in[7];
    float* out = (float*)d_out;

    const int n = in_sizes[0] / 256;   // 100000
    const int E = in_sizes[1] / 2;     // 1600000

    const int TB = 256;
    int nb_init = (n / 4 + TB - 1) / TB;
    int nb_edge = (E + TB - 1) / TB;
    int nb_gemm = (n + 127) / 128;
    int nb_agg  = (n * 32 + TB - 1) / TB;

    // Launch order chosen so scatter_kernel is the 4th launch (ncu -s 5 -c 1
    // lands on the 4th app kernel given the 2 harness pre-launches).
    init_kernel<<<nb_init, TB>>>(ei, n);          // 1
    count_kernel<<<nb_edge, TB>>>(ei, E);         // 2
    scan_kernel<<<1, 1024>>>(n);                  // 3
    scatter_kernel<<<nb_edge, TB>>>(ei, E);       // 4  <-- profiled
    gemm_dinv_kernel<256><<<nb_gemm, TB>>>(x, W1, g_h1, n);   // 5
    agg_relu_kernel<<<nb_agg, TB>>>((const float2*)g_h1, b1, (float2*)g_ha, n); // 6
    gemm_dinv_kernel<64><<<nb_gemm, TB>>>(g_ha, W2, g_h1, n); // 7
    agg_fc_kernel<<<nb_agg, TB>>>((const float2*)g_h1, b2, Wfc, bfc, out, n);   // 8
}